// round 4
// baseline (speedup 1.0000x reference)
#include <cuda_runtime.h>

#define N_NODES  50000
#define N_EDGES_MAX 800000
#define HID      128
#define IN_DIM   64
#define OUT_DIM  10
#define N_GRAPHS 64

// ---------------- scratch (static device globals; referenced ONLY in device code)
__device__ int   g_cnt_i[N_NODES];                 // per-node in-degree (excl self)
__device__ int   g_rowptr[N_NODES + 1];
__device__ int   g_fill[N_NODES];
__device__ int   g_csr[N_EDGES_MAX];               // src ids grouped by dst
__device__ float g_dinv[N_NODES];
__device__ float g_xs[(size_t)N_NODES * IN_DIM];   // dinv * x
__device__ float g_y1[(size_t)N_NODES * IN_DIM];   // dinv * (A+I) * xs
__device__ float g_h1s[(size_t)N_NODES * HID];     // dinv * relu(y1 W1^T + b1)
__device__ float g_y2[(size_t)N_NODES * HID];      // dinv * (A+I) * h1s
__device__ float g_pool[N_GRAPHS * HID];
__device__ float g_cnt[N_GRAPHS];

// ---------------- init / degree / scan / fill --------------------------------
__global__ void init_kernel() {
    int i = blockIdx.x * blockDim.x + threadIdx.x;
    if (i < N_NODES) g_cnt_i[i] = 0;
    if (i < N_GRAPHS * HID) g_pool[i] = 0.0f;
    if (i < N_GRAPHS) g_cnt[i] = 0.0f;
}

__global__ void count_kernel(const int* __restrict__ ei, int E) {
    int i = blockIdx.x * blockDim.x + threadIdx.x;
    if (i < E) atomicAdd(&g_cnt_i[ei[E + i]], 1);
}

__global__ void __launch_bounds__(1024) scan_kernel() {
    __shared__ int partial[1024];
    const int ITEMS = (N_NODES + 1023) / 1024;   // 49
    int t = threadIdx.x;
    int beg = t * ITEMS;
    int s = 0;
    for (int i = 0; i < ITEMS; i++) {
        int idx = beg + i;
        if (idx < N_NODES) s += g_cnt_i[idx];
    }
    partial[t] = s;
    __syncthreads();
    for (int off = 1; off < 1024; off <<= 1) {
        int u = (t >= off) ? partial[t - off] : 0;
        __syncthreads();
        partial[t] += u;
        __syncthreads();
    }
    int run = partial[t] - s;   // exclusive prefix of this chunk
    for (int i = 0; i < ITEMS; i++) {
        int idx = beg + i;
        if (idx < N_NODES) {
            int c = g_cnt_i[idx];
            g_rowptr[idx] = run;
            g_fill[idx]   = run;
            g_dinv[idx]   = rsqrtf((float)c + 1.0f);  // +1 self loop
            run += c;
        }
    }
    if (t == 1023) g_rowptr[N_NODES] = run;
}

__global__ void fill_kernel(const int* __restrict__ ei, int E) {
    int i = blockIdx.x * blockDim.x + threadIdx.x;
    if (i < E) {
        int d = ei[E + i];
        int p = atomicAdd(&g_fill[d], 1);
        g_csr[p] = ei[i];
    }
}

// xs = dinv * x, plus graph node counts
__global__ void scale_x_kernel(const float* __restrict__ x,
                               const int* __restrict__ batch) {
    int idx = blockIdx.x * blockDim.x + threadIdx.x;   // float4 index
    if (idx >= N_NODES * (IN_DIM / 4)) return;
    int n = idx / (IN_DIM / 4);
    float dv = g_dinv[n];
    float4 v = ((const float4*)x)[idx];
    v.x *= dv; v.y *= dv; v.z *= dv; v.w *= dv;
    ((float4*)g_xs)[idx] = v;
    if ((idx & (IN_DIM / 4 - 1)) == 0)
        atomicAdd(&g_cnt[__ldg(batch + n)], 1.0f);
}

// ---------------- CSR gather aggregation: out = dinv * (feat[node] + sum feat[src])
// LAYER2=false: g_xs  -> g_y1  (64-dim,  float2/lane)
// LAYER2=true : g_h1s -> g_y2  (128-dim, float4/lane)
template <bool LAYER2>
__global__ void agg_kernel() {
    const float* __restrict__ feat = LAYER2 ? g_h1s : g_xs;
    float* __restrict__ out        = LAYER2 ? g_y2  : g_y1;
    const int DIM = LAYER2 ? 128 : 64;

    int warp = (blockIdx.x * blockDim.x + threadIdx.x) >> 5;
    if (warp >= N_NODES) return;
    int lane = threadIdx.x & 31;

    if (!LAYER2) {
        float2 acc = *(const float2*)(feat + (size_t)warp * DIM + lane * 2);
        int beg = g_rowptr[warp], end = g_rowptr[warp + 1];
        for (int base = beg; base < end; base += 32) {
            int idx = (base + lane < end) ? g_csr[base + lane] : 0;
            int n = min(32, end - base);
            int j = 0;
            for (; j + 4 <= n; j += 4) {
                int s0 = __shfl_sync(0xFFFFFFFFu, idx, j);
                int s1 = __shfl_sync(0xFFFFFFFFu, idx, j + 1);
                int s2 = __shfl_sync(0xFFFFFFFFu, idx, j + 2);
                int s3 = __shfl_sync(0xFFFFFFFFu, idx, j + 3);
                float2 v0 = *(const float2*)(feat + (size_t)s0 * DIM + lane * 2);
                float2 v1 = *(const float2*)(feat + (size_t)s1 * DIM + lane * 2);
                float2 v2 = *(const float2*)(feat + (size_t)s2 * DIM + lane * 2);
                float2 v3 = *(const float2*)(feat + (size_t)s3 * DIM + lane * 2);
                acc.x += (v0.x + v1.x) + (v2.x + v3.x);
                acc.y += (v0.y + v1.y) + (v2.y + v3.y);
            }
            for (; j < n; j++) {
                int s = __shfl_sync(0xFFFFFFFFu, idx, j);
                float2 v = *(const float2*)(feat + (size_t)s * DIM + lane * 2);
                acc.x += v.x; acc.y += v.y;
            }
        }
        float dv = g_dinv[warp];
        acc.x *= dv; acc.y *= dv;
        *(float2*)(out + (size_t)warp * DIM + lane * 2) = acc;
    } else {
        float4 acc = *(const float4*)(feat + (size_t)warp * DIM + lane * 4);
        int beg = g_rowptr[warp], end = g_rowptr[warp + 1];
        for (int base = beg; base < end; base += 32) {
            int idx = (base + lane < end) ? g_csr[base + lane] : 0;
            int n = min(32, end - base);
            int j = 0;
            for (; j + 4 <= n; j += 4) {
                int s0 = __shfl_sync(0xFFFFFFFFu, idx, j);
                int s1 = __shfl_sync(0xFFFFFFFFu, idx, j + 1);
                int s2 = __shfl_sync(0xFFFFFFFFu, idx, j + 2);
                int s3 = __shfl_sync(0xFFFFFFFFu, idx, j + 3);
                float4 v0 = *(const float4*)(feat + (size_t)s0 * DIM + lane * 4);
                float4 v1 = *(const float4*)(feat + (size_t)s1 * DIM + lane * 4);
                float4 v2 = *(const float4*)(feat + (size_t)s2 * DIM + lane * 4);
                float4 v3 = *(const float4*)(feat + (size_t)s3 * DIM + lane * 4);
                acc.x += (v0.x + v1.x) + (v2.x + v3.x);
                acc.y += (v0.y + v1.y) + (v2.y + v3.y);
                acc.z += (v0.z + v1.z) + (v2.z + v3.z);
                acc.w += (v0.w + v1.w) + (v2.w + v3.w);
            }
            for (; j < n; j++) {
                int s = __shfl_sync(0xFFFFFFFFu, idx, j);
                float4 v = *(const float4*)(feat + (size_t)s * DIM + lane * 4);
                acc.x += v.x; acc.y += v.y; acc.z += v.z; acc.w += v.w;
            }
        }
        float dv = g_dinv[warp];
        acc.x *= dv; acc.y *= dv; acc.z *= dv; acc.w *= dv;
        *(float4*)(out + (size_t)warp * DIM + lane * 4) = acc;
    }
}

// ---------------- GEMM: 128x128 tile, 256 threads, 8x8 per thread (scalar FFMA)
// LAYER2=false: g_h1s[row] = dinv[row] * relu(g_y1 W^T + b)   (K=64)
// LAYER2=true : g_pool[batch[row]] += relu(g_y2 W^T + b)      (K=128)
template <bool LAYER2>
__global__ void __launch_bounds__(256) gemm_kernel(const float* __restrict__ W,
                                                   const float* __restrict__ bias,
                                                   const int* __restrict__ batch) {
    const int K = LAYER2 ? HID : IN_DIM;
    const float* __restrict__ Xin = LAYER2 ? g_y2 : g_y1;

    __shared__ float ws[32][136];   // [k][col]
    __shared__ float xs[32][136];   // [k][row]

    int tid = threadIdx.x;
    int ty = tid >> 4;     // 0..15 row group
    int tx = tid & 15;     // 0..15 col group
    int row0 = blockIdx.x * 128;

    float acc[8][8] = {};

    for (int kc = 0; kc < K; kc += 32) {
        for (int i = tid; i < 128 * 32; i += 256) {
            int c = i >> 5, k = i & 31;
            ws[k][c] = W[c * K + kc + k];
        }
        for (int i = tid; i < 128 * 32; i += 256) {
            int r = i >> 5, k = i & 31;
            int row = row0 + r;
            xs[k][r] = (row < N_NODES) ? Xin[(size_t)row * K + kc + k] : 0.0f;
        }
        __syncthreads();

#pragma unroll
        for (int k = 0; k < 32; k++) {
            float4 a0 = *(const float4*)&xs[k][ty * 8];
            float4 a1 = *(const float4*)&xs[k][ty * 8 + 4];
            float4 b0 = *(const float4*)&ws[k][tx * 8];
            float4 b1 = *(const float4*)&ws[k][tx * 8 + 4];
            float av[8] = {a0.x, a0.y, a0.z, a0.w, a1.x, a1.y, a1.z, a1.w};
            float bv[8] = {b0.x, b0.y, b0.z, b0.w, b1.x, b1.y, b1.z, b1.w};
#pragma unroll
            for (int i = 0; i < 8; i++)
#pragma unroll
                for (int j = 0; j < 8; j++)
                    acc[i][j] = fmaf(av[i], bv[j], acc[i][j]);
        }
        __syncthreads();
    }

    float4 bb0 = *(const float4*)&bias[tx * 8];
    float4 bb1 = *(const float4*)&bias[tx * 8 + 4];
    float bv[8] = {bb0.x, bb0.y, bb0.z, bb0.w, bb1.x, bb1.y, bb1.z, bb1.w};

#pragma unroll
    for (int i = 0; i < 8; i++) {
        int row = row0 + ty * 8 + i;
        if (row < N_NODES) {
            float r[8];
#pragma unroll
            for (int j = 0; j < 8; j++)
                r[j] = fmaxf(acc[i][j] + bv[j], 0.0f);
            if (!LAYER2) {
                float dv = g_dinv[row];
                float4 v0 = make_float4(r[0] * dv, r[1] * dv, r[2] * dv, r[3] * dv);
                float4 v1 = make_float4(r[4] * dv, r[5] * dv, r[6] * dv, r[7] * dv);
                *(float4*)&g_h1s[(size_t)row * HID + tx * 8] = v0;
                *(float4*)&g_h1s[(size_t)row * HID + tx * 8 + 4] = v1;
            } else {
                float* dst = g_pool + (size_t)__ldg(batch + row) * HID + tx * 8;
                asm volatile("red.global.add.v4.f32 [%0], {%1, %2, %3, %4};"
                             :: "l"(dst), "f"(r[0]), "f"(r[1]), "f"(r[2]), "f"(r[3])
                             : "memory");
                asm volatile("red.global.add.v4.f32 [%0], {%1, %2, %3, %4};"
                             :: "l"(dst + 4), "f"(r[4]), "f"(r[5]), "f"(r[6]), "f"(r[7])
                             : "memory");
            }
        }
    }
}

// ---------------- final: out[g][o] = pooled[g] . fc_w[o] + fc_b[o] -----------
__global__ void final_kernel(const float* __restrict__ fcw,
                             const float* __restrict__ fcb,
                             float* __restrict__ out) {
    int g = blockIdx.x;
    int lane = threadIdx.x;
    float inv = 1.0f / fmaxf(g_cnt[g], 1.0f);
    float p[4];
#pragma unroll
    for (int j = 0; j < 4; j++) p[j] = g_pool[g * HID + j * 32 + lane] * inv;
#pragma unroll
    for (int o = 0; o < OUT_DIM; o++) {
        float s = 0.0f;
#pragma unroll
        for (int j = 0; j < 4; j++) s += p[j] * fcw[o * HID + j * 32 + lane];
#pragma unroll
        for (int off = 16; off; off >>= 1) s += __shfl_down_sync(0xFFFFFFFFu, s, off);
        if (lane == 0) out[g * OUT_DIM + o] = s + fcb[o];
    }
}

// ---------------- launch ------------------------------------------------------
extern "C" void kernel_launch(void* const* d_in, const int* in_sizes, int n_in,
                              void* d_out, int out_size) {
    const float* x     = (const float*)d_in[0];
    const int*   ei    = (const int*)  d_in[1];
    const int*   batch = (const int*)  d_in[2];
    const float* w1    = (const float*)d_in[3];
    const float* b1    = (const float*)d_in[4];
    const float* w2    = (const float*)d_in[5];
    const float* b2    = (const float*)d_in[6];
    const float* fcw   = (const float*)d_in[7];
    const float* fcb   = (const float*)d_in[8];
    float* out = (float*)d_out;
    int E = in_sizes[1] / 2;

    int nblk = (N_NODES + 255) / 256;
    int eblk = (E + 255) / 256;

    init_kernel<<<nblk, 256>>>();
    count_kernel<<<eblk, 256>>>(ei, E);
    scan_kernel<<<1, 1024>>>();
    fill_kernel<<<eblk, 256>>>(ei, E);
    scale_x_kernel<<<(N_NODES * 16 + 255) / 256, 256>>>(x, batch);

    int agg_blocks = (N_NODES * 32 + 255) / 256;   // one warp per node
    int gemm_blocks = (N_NODES + 127) / 128;

    // layer 1: aggregate (64-dim) then GEMM
    agg_kernel<false><<<agg_blocks, 256>>>();
    gemm_kernel<false><<<gemm_blocks, 256>>>(w1, b1, nullptr);

    // layer 2: aggregate (128-dim) then GEMM + fused mean-pool accumulation
    agg_kernel<true><<<agg_blocks, 256>>>();
    gemm_kernel<true><<<gemm_blocks, 256>>>(w2, b2, batch);

    final_kernel<<<N_GRAPHS, 32>>>(fcw, fcb, out);
}